// round 2
// baseline (speedup 1.0000x reference)
#include <cuda_runtime.h>
#include <float.h>

// ---------------- output layout (x_hat, idx, vq_loss, z_e) flattened fp32 ----
#define XHAT_OFF 0
#define IDX_OFF  1572864
#define LOSS_OFF 1574912
#define ZE_OFF   1574913

// ---------------- scratch ---------------------------------------------------
__device__ float g_h1[32*128*64*64];     // encoder conv1 out (B,128,64,64)
__device__ float g_h2[32*128*32*32];     // encoder conv2 out (B,128,32,32)
__device__ float g_pool[32*128*8*8];     // pooled (B,128,8,8)
__device__ float g_v[2048*128];          // relu(dproj(z_q)) per grid cell [n][oc]
__device__ float g_wprep[9*128*128];     // aggregated dconv1 weights [m][ic][oc]
__device__ float g_w2t[128*9*128];       // enc conv2 weights transposed [(ic*9+tap)][oc]
__device__ float g_partial[2048];        // per-position loss partials

// ---------------- encoder conv1: (B,3,128,128) -> (B,128,64,64), s2 p1, ReLU --
__global__ __launch_bounds__(128) void conv1_kernel(
    const float* __restrict__ x, const float* __restrict__ w,
    const float* __restrict__ bias)
{
    const int oc  = threadIdx.x;
    const int ox0 = blockIdx.x * 32;
    const int oy  = blockIdx.y;
    const int b   = blockIdx.z;
    __shared__ float s_in[3][3][66];
    __shared__ float s_out[128][33];

    for (int e = threadIdx.x; e < 3*3*66; e += 128) {
        int ic  = e / (3*66);
        int rem = e % (3*66);
        int ky  = rem / 66;
        int col = rem % 66;
        int ix  = 2*ox0 - 1 + col;
        int iy  = 2*oy  - 1 + ky;
        float v = 0.f;
        if (ix >= 0 && ix < 128 && iy >= 0 && iy < 128)
            v = x[((b*3 + ic)*128 + iy)*128 + ix];
        s_in[ic][ky][col] = v;
    }
    __syncthreads();

    float acc[32];
#pragma unroll
    for (int i = 0; i < 32; i++) acc[i] = 0.f;

#pragma unroll
    for (int ic = 0; ic < 3; ic++)
#pragma unroll
    for (int ky = 0; ky < 3; ky++)
#pragma unroll
    for (int kx = 0; kx < 3; kx++) {
        float wv = w[((oc*3 + ic)*3 + ky)*3 + kx];
#pragma unroll
        for (int ox = 0; ox < 32; ox++)
            acc[ox] = fmaf(wv, s_in[ic][ky][2*ox + kx], acc[ox]);
    }

    float bv = bias[oc];
#pragma unroll
    for (int ox = 0; ox < 32; ox++) {
        float v = acc[ox] + bv;
        s_out[oc][ox] = v > 0.f ? v : 0.f;
    }
    __syncthreads();
    for (int e = threadIdx.x; e < 128*32; e += 128) {
        int o = e >> 5, xw = e & 31;
        g_h1[((b*128 + o)*64 + oy)*64 + ox0 + xw] = s_out[o][xw];
    }
}

// ---------------- transpose conv2 weights for coalesced loads ---------------
__global__ void w2t_kernel(const float* __restrict__ w)
{
    int t = blockIdx.x*256 + threadIdx.x;
    if (t >= 128*9*128) return;
    int oc = t & 127;
    int rest = t >> 7;
    int tap = rest % 9;
    int ic  = rest / 9;
    g_w2t[t] = w[(oc*128 + ic)*9 + tap];
}

// ---------------- encoder conv2: (B,128,64,64) -> (B,128,32,32), s2 p1, ReLU -
__global__ __launch_bounds__(128) void conv2_kernel(const float* __restrict__ bias)
{
    const int oc = threadIdx.x;
    const int oy = blockIdx.x;
    const int b  = blockIdx.y;
    __shared__ float s_in[32][3][66];
    __shared__ float s_out[128][33];

    float acc[32];
#pragma unroll
    for (int i = 0; i < 32; i++) acc[i] = 0.f;

    for (int c0 = 0; c0 < 128; c0 += 32) {
        __syncthreads();
        for (int e = threadIdx.x; e < 32*3*66; e += 128) {
            int ic  = e / (3*66);
            int rem = e % (3*66);
            int ky  = rem / 66;
            int col = rem % 66;
            int ix  = col - 1;
            int iy  = 2*oy - 1 + ky;
            float v = 0.f;
            if (ix >= 0 && ix < 64 && iy >= 0 && iy < 64)
                v = g_h1[((b*128 + c0 + ic)*64 + iy)*64 + ix];
            s_in[ic][ky][col] = v;
        }
        __syncthreads();

        for (int ic = 0; ic < 32; ic++) {
            const float* wp = &g_w2t[(c0 + ic)*9*128 + oc];
#pragma unroll
            for (int ky = 0; ky < 3; ky++)
#pragma unroll
            for (int kx = 0; kx < 3; kx++) {
                float wv = wp[(ky*3 + kx)*128];
#pragma unroll
                for (int ox = 0; ox < 32; ox++)
                    acc[ox] = fmaf(wv, s_in[ic][ky][2*ox + kx], acc[ox]);
            }
        }
    }

    float bv = bias[oc];
#pragma unroll
    for (int ox = 0; ox < 32; ox++) {
        float v = acc[ox] + bv;
        s_out[oc][ox] = v > 0.f ? v : 0.f;
    }
    __syncthreads();
    for (int e = threadIdx.x; e < 128*32; e += 128) {
        int o = e >> 5, xw = e & 31;
        g_h2[((b*128 + o)*32 + oy)*32 + xw] = s_out[o][xw];
    }
}

// ---------------- 4x4 avg pool: (B,128,32,32) -> (B,128,8,8) ----------------
__global__ void pool_kernel()
{
    int t = blockIdx.x*256 + threadIdx.x;
    if (t >= 32*128*64) return;
    int gw = t & 7, gh = (t >> 3) & 7, c = (t >> 6) & 127, b = t >> 13;
    const float* base = &g_h2[((b*128 + c)*32 + gh*4)*32 + gw*4];
    float s = 0.f;
#pragma unroll
    for (int i = 0; i < 4; i++)
#pragma unroll
    for (int j = 0; j < 4; j++) s += base[i*32 + j];
    g_pool[t] = s * (1.f/16.f);
}

// ---------------- proj + VQ + dproj fused, one block per grid cell ----------
__global__ __launch_bounds__(128) void projvq_kernel(
    const float* __restrict__ proj_w, const float* __restrict__ proj_b,
    const float* __restrict__ cb,
    const float* __restrict__ dproj_w, const float* __restrict__ dproj_b,
    float* __restrict__ out)
{
    int n = blockIdx.x;                       // b*64 + gh*8 + gw
    int b = n >> 6, gh = (n >> 3) & 7, gw = n & 7;
    int tid = threadIdx.x;
    __shared__ float z[64];
    __shared__ float zq[64];
    __shared__ float red[128];
    __shared__ int   redi[128];

    if (tid < 64) {
        float s = proj_b[tid];
        const float* pw = &proj_w[tid*128];
        for (int c = 0; c < 128; c++)
            s = fmaf(pw[c], g_pool[((b*128 + c)*8 + gh)*8 + gw], s);
        z[tid] = s;
        out[ZE_OFF + ((b*64 + tid)*8 + gh)*8 + gw] = s;
    }
    __syncthreads();

    float best = FLT_MAX; int bi = 0;
    for (int kk = 0; kk < 4; kk++) {
        int k = tid*4 + kk;
        const float* ck = &cb[k*64];
        float d2 = 0.f;
#pragma unroll 16
        for (int d = 0; d < 64; d++) { float df = z[d] - ck[d]; d2 = fmaf(df, df, d2); }
        if (d2 < best) { best = d2; bi = k; }
    }
    red[tid] = best; redi[tid] = bi;
    __syncthreads();
    for (int s = 64; s > 0; s >>= 1) {
        if (tid < s) {
            float d2 = red[tid + s]; int k2 = redi[tid + s];
            if (d2 < red[tid] || (d2 == red[tid] && k2 < redi[tid])) {
                red[tid] = d2; redi[tid] = k2;
            }
        }
        __syncthreads();
    }
    int idx = redi[0];
    if (tid == 0) out[IDX_OFF + n] = (float)idx;
    if (tid < 64) zq[tid] = cb[idx*64 + tid];
    __syncthreads();

    // loss partial: sum_d (zq - z)^2 (deterministic tree)
    if (tid < 64) { float df = zq[tid] - z[tid]; red[tid] = df*df; }
    __syncthreads();
    if (tid < 32) red[tid] += red[tid + 32];  __syncthreads();
    if (tid < 16) red[tid] += red[tid + 16];  __syncthreads();
    if (tid <  8) red[tid] += red[tid +  8];  __syncthreads();
    if (tid <  4) red[tid] += red[tid +  4];  __syncthreads();
    if (tid <  2) red[tid] += red[tid +  2];  __syncthreads();
    if (tid == 0) g_partial[n] = red[0] + red[1];

    // dproj (1x1, 64->128) + ReLU, store [n][oc]
    float s2 = dproj_b[tid];
    const float* dw = &dproj_w[tid*64];
#pragma unroll 16
    for (int d = 0; d < 64; d++) s2 = fmaf(dw[d], zq[d], s2);
    g_v[n*128 + tid] = s2 > 0.f ? s2 : 0.f;
}

// ---------------- loss reduce -----------------------------------------------
__global__ void loss_kernel(float* __restrict__ out)
{
    __shared__ float s[1024];
    int t = threadIdx.x;
    s[t] = g_partial[t] + g_partial[t + 1024];
    __syncthreads();
    for (int k = 512; k > 0; k >>= 1) {
        if (t < k) s[t] += s[t + k];
        __syncthreads();
    }
    if (t == 0) out[LOSS_OFF] = 1.25f * s[0] / (2048.f * 64.f);
}

// ---------------- aggregated dconv1 weights ---------------------------------
// m: 0=sum_all 1=row_top 2=row_bot 3=col_left 4=col_right 5=tl 6=tr 7=bl 8=br
__global__ void wprep_kernel(const float* __restrict__ w)
{
    int t = blockIdx.x*128 + threadIdx.x;     // 16384
    int oc = t & 127, ic = t >> 7;
    const float* wp = &w[(oc*128 + ic)*9];
    float W[9];
#pragma unroll
    for (int i = 0; i < 9; i++) W[i] = wp[i];
    float S  = W[0]+W[1]+W[2]+W[3]+W[4]+W[5]+W[6]+W[7]+W[8];
    float Rt = W[0]+W[1]+W[2];
    float Rb = W[6]+W[7]+W[8];
    float Cl = W[0]+W[3]+W[6];
    float Cr = W[2]+W[5]+W[8];
    float out9[9] = {S, Rt, Rb, Cl, Cr, W[0], W[2], W[6], W[8]};
#pragma unroll
    for (int m = 0; m < 9; m++)
        g_wprep[(m*128 + ic)*128 + oc] = out9[m];
}

// ---------------- decoder: block-structured dconv1 + ReLU + dconv2 ----------
// Upsampled input is constant per 16x16 block -> only 9 distinct outputs per
// block (corner/edge/interior), each a combo of 9 precomputed 128x128 matvecs.
__global__ __launch_bounds__(128) void dec_kernel(
    const float* __restrict__ b1, const float* __restrict__ w2,
    const float* __restrict__ b2, float* __restrict__ out)
{
    int n = blockIdx.x;
    int b = n >> 6, gh = (n >> 3) & 7, gw = n & 7;
    int tid = threadIdx.x;
    __shared__ float comb[9][128];
    __shared__ float hcat[9][128];
    __shared__ float rpart[27][4];
    __shared__ float rgbs[27];

    float v00 = g_v[n*128 + tid];
    float va  = gh > 0            ? g_v[(n-8)*128 + tid] : 0.f;
    float vb  = gh < 7            ? g_v[(n+8)*128 + tid] : 0.f;
    float vl  = gw > 0            ? g_v[(n-1)*128 + tid] : 0.f;
    float vr  = gw < 7            ? g_v[(n+1)*128 + tid] : 0.f;
    float vtl = (gh > 0 && gw > 0) ? g_v[(n-9)*128 + tid] : 0.f;
    float vtr = (gh > 0 && gw < 7) ? g_v[(n-7)*128 + tid] : 0.f;
    float vbl = (gh < 7 && gw > 0) ? g_v[(n+7)*128 + tid] : 0.f;
    float vbr = (gh < 7 && gw < 7) ? g_v[(n+9)*128 + tid] : 0.f;

    comb[0][tid] = v00;
    comb[1][tid] = va - v00;
    comb[2][tid] = vb - v00;
    comb[3][tid] = vl - v00;
    comb[4][tid] = vr - v00;
    comb[5][tid] = vtl - va - vl + v00;
    comb[6][tid] = vtr - va - vr + v00;
    comb[7][tid] = vbl - vb - vl + v00;
    comb[8][tid] = vbr - vb - vr + v00;
    __syncthreads();

    float a[9];
#pragma unroll
    for (int m = 0; m < 9; m++) a[m] = 0.f;
    for (int ic = 0; ic < 128; ic++) {
#pragma unroll
        for (int m = 0; m < 9; m++)
            a[m] = fmaf(g_wprep[(m*128 + ic)*128 + tid], comb[m][ic], a[m]);
    }

    float base = a[0] + b1[tid];
    float hm[9];
    hm[4] = base;
    hm[1] = base + a[1];
    hm[7] = base + a[2];
    hm[3] = base + a[3];
    hm[5] = base + a[4];
    hm[0] = base + a[1] + a[3] + a[5];
    hm[2] = base + a[1] + a[4] + a[6];
    hm[6] = base + a[2] + a[3] + a[7];
    hm[8] = base + a[2] + a[4] + a[8];
#pragma unroll
    for (int c = 0; c < 9; c++) hcat[c][tid] = hm[c] > 0.f ? hm[c] : 0.f;
    __syncthreads();

    if (tid < 108) {
        int ch = tid / 36, rem = tid % 36, cat = rem >> 2, part = rem & 3;
        const float* wc = &w2[ch*128 + part*32];
        const float* hc = &hcat[cat][part*32];
        float s = 0.f;
#pragma unroll
        for (int i = 0; i < 32; i++) s = fmaf(wc[i], hc[i], s);
        rpart[ch*9 + cat][part] = s;
    }
    __syncthreads();
    if (tid < 27) {
        int ch = tid / 9;
        rgbs[tid] = rpart[tid][0] + rpart[tid][1] + rpart[tid][2] + rpart[tid][3] + b2[ch];
    }
    __syncthreads();

    int y0 = gh*16, x0 = gw*16;
    for (int p = tid; p < 768; p += 128) {
        int ch = p >> 8, rem = p & 255, r = rem >> 4, c = rem & 15;
        int rcat = (r == 0) ? 0 : ((r == 15) ? 2 : 1);
        int ccat = (c == 0) ? 0 : ((c == 15) ? 2 : 1);
        out[XHAT_OFF + ((b*3 + ch)*128 + y0 + r)*128 + x0 + c] = rgbs[ch*9 + rcat*3 + ccat];
    }
}

// ---------------- launch ----------------------------------------------------
extern "C" void kernel_launch(void* const* d_in, const int* in_sizes, int n_in,
                              void* d_out, int out_size)
{
    const float* x        = (const float*)d_in[0];
    const float* enc_w1   = (const float*)d_in[1];
    const float* enc_b1   = (const float*)d_in[2];
    const float* enc_w2   = (const float*)d_in[3];
    const float* enc_b2   = (const float*)d_in[4];
    const float* proj_w   = (const float*)d_in[5];
    const float* proj_b   = (const float*)d_in[6];
    const float* codebook = (const float*)d_in[7];
    const float* dproj_w  = (const float*)d_in[8];
    const float* dproj_b  = (const float*)d_in[9];
    const float* dconv1_w = (const float*)d_in[10];
    const float* dconv1_b = (const float*)d_in[11];
    const float* dconv2_w = (const float*)d_in[12];
    const float* dconv2_b = (const float*)d_in[13];
    float* out = (float*)d_out;

    conv1_kernel<<<dim3(2, 64, 32), 128>>>(x, enc_w1, enc_b1);
    w2t_kernel<<<576, 256>>>(enc_w2);
    conv2_kernel<<<dim3(32, 32), 128>>>(enc_b2);
    pool_kernel<<<1024, 256>>>();
    wprep_kernel<<<128, 128>>>(dconv1_w);
    projvq_kernel<<<2048, 128>>>(proj_w, proj_b, codebook, dproj_w, dproj_b, out);
    loss_kernel<<<1, 1024>>>(out);
    dec_kernel<<<2048, 128>>>(dconv1_b, dconv2_w, dconv2_b, out);
}

// round 4
// speedup vs baseline: 1.5736x; 1.5736x over previous
#include <cuda_runtime.h>
#include <float.h>

// ---------------- output layout (x_hat, idx, vq_loss, z_e) flattened fp32 ----
#define XHAT_OFF 0
#define IDX_OFF  1572864
#define LOSS_OFF 1574912
#define ZE_OFF   1574913

// ---------------- scratch ---------------------------------------------------
__device__ float g_h1[32*128*64*64];     // encoder conv1 out (B,128,64,64)
__device__ float g_h2[32*128*32*32];     // encoder conv2 out (B,128,32,32)
__device__ float g_pool[2048*128];       // pooled, layout [n][c], n=b*64+gh*8+gw
__device__ float g_v[2048*128];          // relu(dproj(z_q)) per grid cell [n][oc]
__device__ float g_wprep[9*128*128];     // aggregated dconv1 weights [m][ic][oc]
__device__ float g_w2t[128*9*128];       // enc conv2 weights transposed [(ic*9+tap)][oc]
__device__ float g_partial[2048];        // per-position loss partials

// ---------------- encoder conv1: (B,3,128,128) -> (B,128,64,64), s2 p1, ReLU --
__global__ __launch_bounds__(128) void conv1_kernel(
    const float* __restrict__ x, const float* __restrict__ w,
    const float* __restrict__ bias)
{
    const int oc  = threadIdx.x;
    const int ox0 = blockIdx.x * 32;
    const int oy  = blockIdx.y;
    const int b   = blockIdx.z;
    __shared__ float s_in[3][3][66];
    __shared__ float s_out[128][33];

    for (int e = threadIdx.x; e < 3*3*66; e += 128) {
        int ic  = e / (3*66);
        int rem = e % (3*66);
        int ky  = rem / 66;
        int col = rem % 66;
        int ix  = 2*ox0 - 1 + col;
        int iy  = 2*oy  - 1 + ky;
        float v = 0.f;
        if (ix >= 0 && ix < 128 && iy >= 0 && iy < 128)
            v = x[((b*3 + ic)*128 + iy)*128 + ix];
        s_in[ic][ky][col] = v;
    }
    __syncthreads();

    float acc[32];
#pragma unroll
    for (int i = 0; i < 32; i++) acc[i] = 0.f;

#pragma unroll
    for (int ic = 0; ic < 3; ic++)
#pragma unroll
    for (int ky = 0; ky < 3; ky++)
#pragma unroll
    for (int kx = 0; kx < 3; kx++) {
        float wv = w[((oc*3 + ic)*3 + ky)*3 + kx];
#pragma unroll
        for (int ox = 0; ox < 32; ox++)
            acc[ox] = fmaf(wv, s_in[ic][ky][2*ox + kx], acc[ox]);
    }

    float bv = bias[oc];
#pragma unroll
    for (int ox = 0; ox < 32; ox++) {
        float v = acc[ox] + bv;
        s_out[oc][ox] = v > 0.f ? v : 0.f;
    }
    __syncthreads();
    for (int e = threadIdx.x; e < 128*32; e += 128) {
        int o = e >> 5, xw = e & 31;
        g_h1[((b*128 + o)*64 + oy)*64 + ox0 + xw] = s_out[o][xw];
    }
}

// ---------------- transpose conv2 weights for coalesced loads ---------------
__global__ void w2t_kernel(const float* __restrict__ w)
{
    int t = blockIdx.x*256 + threadIdx.x;
    if (t >= 128*9*128) return;
    int oc = t & 127;
    int rest = t >> 7;
    int tap = rest % 9;
    int ic  = rest / 9;
    g_w2t[t] = w[(oc*128 + ic)*9 + tap];
}

// ---------------- encoder conv2: (B,128,64,64) -> (B,128,32,32), s2 p1, ReLU -
// 256 threads: oc = tid&127, half = tid>>7 covers ox = half*16 + [0,16)
__global__ __launch_bounds__(256) void conv2_kernel(const float* __restrict__ bias)
{
    const int oc   = threadIdx.x & 127;
    const int half = threadIdx.x >> 7;
    const int oy   = blockIdx.x;
    const int b    = blockIdx.y;
    __shared__ float s_in[32][3][72];     // row stride 72 floats -> 16B-aligned rows
    __shared__ float s_out[128][33];

    float acc[16];
#pragma unroll
    for (int i = 0; i < 16; i++) acc[i] = 0.f;

    const int xb = half * 32;             // input column base for this half

    for (int c0 = 0; c0 < 128; c0 += 32) {
        __syncthreads();
        for (int e = threadIdx.x; e < 32*3*66; e += 256) {
            int ic  = e / 198;
            int rem = e % 198;
            int ky  = rem / 66;
            int col = rem % 66;
            int ix  = col - 1;
            int iy  = 2*oy - 1 + ky;
            float v = 0.f;
            if (ix >= 0 && ix < 64 && iy >= 0 && iy < 64)
                v = g_h1[((b*128 + c0 + ic)*64 + iy)*64 + ix];
            s_in[ic][ky][col] = v;
        }
        __syncthreads();

        const float* wbase = &g_w2t[c0*9*128 + oc];
        float wc[9];
#pragma unroll
        for (int t = 0; t < 9; t++) wc[t] = wbase[t*128];

        for (int ic = 0; ic < 32; ic++) {
            float wn[9];
            if (ic < 31) {
                const float* wb2 = wbase + (ic + 1)*9*128;
#pragma unroll
                for (int t = 0; t < 9; t++) wn[t] = wb2[t*128];
            }

#pragma unroll
            for (int ky = 0; ky < 3; ky++) {
                float r[34];
                const float4* rp4 = reinterpret_cast<const float4*>(&s_in[ic][ky][xb]);
#pragma unroll
                for (int g = 0; g < 8; g++) {
                    float4 q = rp4[g];
                    r[4*g + 0] = q.x; r[4*g + 1] = q.y;
                    r[4*g + 2] = q.z; r[4*g + 3] = q.w;
                }
                {
                    const float2* rp2 = reinterpret_cast<const float2*>(&s_in[ic][ky][xb + 32]);
                    float2 q = rp2[0];
                    r[32] = q.x; r[33] = q.y;
                }
                float w0 = wc[ky*3 + 0], w1 = wc[ky*3 + 1], w2v = wc[ky*3 + 2];
#pragma unroll
                for (int j = 0; j < 16; j++) {
                    acc[j] = fmaf(w0,  r[2*j],     acc[j]);
                    acc[j] = fmaf(w1,  r[2*j + 1], acc[j]);
                    acc[j] = fmaf(w2v, r[2*j + 2], acc[j]);
                }
            }

            if (ic < 31) {
#pragma unroll
                for (int t = 0; t < 9; t++) wc[t] = wn[t];
            }
        }
    }

    float bv = bias[oc];
#pragma unroll
    for (int j = 0; j < 16; j++) {
        float v = acc[j] + bv;
        s_out[oc][half*16 + j] = v > 0.f ? v : 0.f;
    }
    __syncthreads();
    for (int e = threadIdx.x; e < 128*32; e += 256) {
        int o = e >> 5, xw = e & 31;
        g_h2[((b*128 + o)*32 + oy)*32 + xw] = s_out[o][xw];
    }
}

// ---------------- 4x4 avg pool: (B,128,32,32) -> [n][c] layout --------------
__global__ void pool_kernel()
{
    int t = blockIdx.x*256 + threadIdx.x;
    if (t >= 32*128*64) return;
    int gw = t & 7, gh = (t >> 3) & 7, c = (t >> 6) & 127, b = t >> 13;
    const float* base = &g_h2[((b*128 + c)*32 + gh*4)*32 + gw*4];
    float s = 0.f;
#pragma unroll
    for (int i = 0; i < 4; i++)
#pragma unroll
    for (int j = 0; j < 4; j++) s += base[i*32 + j];
    int n = b*64 + gh*8 + gw;
    g_pool[n*128 + c] = s * (1.f/16.f);
}

// ---------------- proj + VQ + dproj fused, one block per grid cell ----------
__global__ __launch_bounds__(128) void projvq_kernel(
    const float* __restrict__ proj_w, const float* __restrict__ proj_b,
    const float* __restrict__ cb,
    const float* __restrict__ dproj_w, const float* __restrict__ dproj_b,
    float* __restrict__ out)
{
    int n = blockIdx.x;                       // b*64 + gh*8 + gw
    int b = n >> 6, gh = (n >> 3) & 7, gw = n & 7;
    int tid = threadIdx.x;
    __shared__ float s_pool[128];
    __shared__ float z[64];
    __shared__ float zq[64];
    __shared__ float red[128];
    __shared__ int   redi[128];

    s_pool[tid] = g_pool[n*128 + tid];
    __syncthreads();

    if (tid < 64) {
        float s = proj_b[tid];
        const float4* pw4 = reinterpret_cast<const float4*>(&proj_w[tid*128]);
#pragma unroll 8
        for (int c4 = 0; c4 < 32; c4++) {
            float4 wv = pw4[c4];
            s = fmaf(wv.x, s_pool[4*c4 + 0], s);
            s = fmaf(wv.y, s_pool[4*c4 + 1], s);
            s = fmaf(wv.z, s_pool[4*c4 + 2], s);
            s = fmaf(wv.w, s_pool[4*c4 + 3], s);
        }
        z[tid] = s;
        out[ZE_OFF + ((b*64 + tid)*8 + gh)*8 + gw] = s;
    }
    __syncthreads();

    float best = FLT_MAX; int bi = 0;
    for (int kk = 0; kk < 4; kk++) {
        int k = tid*4 + kk;
        const float4* ck4 = reinterpret_cast<const float4*>(&cb[k*64]);
        float d2 = 0.f;
#pragma unroll
        for (int q = 0; q < 16; q++) {
            float4 cv = ck4[q];
            float d0 = z[4*q + 0] - cv.x; d2 = fmaf(d0, d0, d2);
            float d1 = z[4*q + 1] - cv.y; d2 = fmaf(d1, d1, d2);
            float d3 = z[4*q + 2] - cv.z; d2 = fmaf(d3, d3, d2);
            float d4 = z[4*q + 3] - cv.w; d2 = fmaf(d4, d4, d2);
        }
        if (d2 < best) { best = d2; bi = k; }
    }
    red[tid] = best; redi[tid] = bi;
    __syncthreads();
    for (int s = 64; s > 0; s >>= 1) {
        if (tid < s) {
            float d2 = red[tid + s]; int k2 = redi[tid + s];
            if (d2 < red[tid] || (d2 == red[tid] && k2 < redi[tid])) {
                red[tid] = d2; redi[tid] = k2;
            }
        }
        __syncthreads();
    }
    int idx = redi[0];
    if (tid == 0) out[IDX_OFF + n] = (float)idx;
    if (tid < 64) zq[tid] = cb[idx*64 + tid];
    __syncthreads();

    // loss partial: sum_d (zq - z)^2 (deterministic tree)
    if (tid < 64) { float df = zq[tid] - z[tid]; red[tid] = df*df; }
    __syncthreads();
    if (tid < 32) red[tid] += red[tid + 32];  __syncthreads();
    if (tid < 16) red[tid] += red[tid + 16];  __syncthreads();
    if (tid <  8) red[tid] += red[tid +  8];  __syncthreads();
    if (tid <  4) red[tid] += red[tid +  4];  __syncthreads();
    if (tid <  2) red[tid] += red[tid +  2];  __syncthreads();
    if (tid == 0) g_partial[n] = red[0] + red[1];

    // dproj (1x1, 64->128) + ReLU, store [n][oc]
    float s2 = dproj_b[tid];
    const float4* dw4 = reinterpret_cast<const float4*>(&dproj_w[tid*64]);
#pragma unroll
    for (int q = 0; q < 16; q++) {
        float4 wv = dw4[q];
        s2 = fmaf(wv.x, zq[4*q + 0], s2);
        s2 = fmaf(wv.y, zq[4*q + 1], s2);
        s2 = fmaf(wv.z, zq[4*q + 2], s2);
        s2 = fmaf(wv.w, zq[4*q + 3], s2);
    }
    g_v[n*128 + tid] = s2 > 0.f ? s2 : 0.f;
}

// ---------------- loss reduce -----------------------------------------------
__global__ void loss_kernel(float* __restrict__ out)
{
    __shared__ float s[1024];
    int t = threadIdx.x;
    s[t] = g_partial[t] + g_partial[t + 1024];
    __syncthreads();
    for (int k = 512; k > 0; k >>= 1) {
        if (t < k) s[t] += s[t + k];
        __syncthreads();
    }
    if (t == 0) out[LOSS_OFF] = 1.25f * s[0] / (2048.f * 64.f);
}

// ---------------- aggregated dconv1 weights ---------------------------------
// m: 0=sum_all 1=row_top 2=row_bot 3=col_left 4=col_right 5=tl 6=tr 7=bl 8=br
__global__ void wprep_kernel(const float* __restrict__ w)
{
    int t = blockIdx.x*128 + threadIdx.x;     // 16384
    int oc = t & 127, ic = t >> 7;
    const float* wp = &w[(oc*128 + ic)*9];
    float W[9];
#pragma unroll
    for (int i = 0; i < 9; i++) W[i] = wp[i];
    float S  = W[0]+W[1]+W[2]+W[3]+W[4]+W[5]+W[6]+W[7]+W[8];
    float Rt = W[0]+W[1]+W[2];
    float Rb = W[6]+W[7]+W[8];
    float Cl = W[0]+W[3]+W[6];
    float Cr = W[2]+W[5]+W[8];
    float out9[9] = {S, Rt, Rb, Cl, Cr, W[0], W[2], W[6], W[8]};
#pragma unroll
    for (int m = 0; m < 9; m++)
        g_wprep[(m*128 + ic)*128 + oc] = out9[m];
}

// ---------------- decoder: block-structured dconv1 + ReLU + dconv2 ----------
// 4 grid cells per block: g_wprep L2 traffic cut 4x (1.2GB -> 0.3GB).
__global__ __launch_bounds__(128) void dec_kernel(
    const float* __restrict__ b1, const float* __restrict__ w2,
    const float* __restrict__ b2, float* __restrict__ out)
{
    int n0  = blockIdx.x * 4;
    int tid = threadIdx.x;
    __shared__ float s_comb[4][9][128];
    __shared__ float s_hcat[4][9][128];
    __shared__ float s_rgb[4][27];

#pragma unroll
    for (int cell = 0; cell < 4; cell++) {
        int n = n0 + cell;
        int gh = (n >> 3) & 7, gw = n & 7;
        float v00 = g_v[n*128 + tid];
        float va  = gh > 0             ? g_v[(n-8)*128 + tid] : 0.f;
        float vb  = gh < 7             ? g_v[(n+8)*128 + tid] : 0.f;
        float vl  = gw > 0             ? g_v[(n-1)*128 + tid] : 0.f;
        float vr  = gw < 7             ? g_v[(n+1)*128 + tid] : 0.f;
        float vtl = (gh > 0 && gw > 0) ? g_v[(n-9)*128 + tid] : 0.f;
        float vtr = (gh > 0 && gw < 7) ? g_v[(n-7)*128 + tid] : 0.f;
        float vbl = (gh < 7 && gw > 0) ? g_v[(n+7)*128 + tid] : 0.f;
        float vbr = (gh < 7 && gw < 7) ? g_v[(n+9)*128 + tid] : 0.f;

        s_comb[cell][0][tid] = v00;
        s_comb[cell][1][tid] = va - v00;
        s_comb[cell][2][tid] = vb - v00;
        s_comb[cell][3][tid] = vl - v00;
        s_comb[cell][4][tid] = vr - v00;
        s_comb[cell][5][tid] = vtl - va - vl + v00;
        s_comb[cell][6][tid] = vtr - va - vr + v00;
        s_comb[cell][7][tid] = vbl - vb - vl + v00;
        s_comb[cell][8][tid] = vbr - vb - vr + v00;
    }
    __syncthreads();

    float a[4][9];
#pragma unroll
    for (int cell = 0; cell < 4; cell++)
#pragma unroll
        for (int m = 0; m < 9; m++) a[cell][m] = 0.f;

    for (int ic = 0; ic < 128; ic++) {
#pragma unroll
        for (int m = 0; m < 9; m++) {
            float wv = g_wprep[(m*128 + ic)*128 + tid];
#pragma unroll
            for (int cell = 0; cell < 4; cell++)
                a[cell][m] = fmaf(wv, s_comb[cell][m][ic], a[cell][m]);
        }
    }

    float bv = b1[tid];
#pragma unroll
    for (int cell = 0; cell < 4; cell++) {
        float base = a[cell][0] + bv;
        float hm[9];
        hm[4] = base;
        hm[1] = base + a[cell][1];
        hm[7] = base + a[cell][2];
        hm[3] = base + a[cell][3];
        hm[5] = base + a[cell][4];
        hm[0] = base + a[cell][1] + a[cell][3] + a[cell][5];
        hm[2] = base + a[cell][1] + a[cell][4] + a[cell][6];
        hm[6] = base + a[cell][2] + a[cell][3] + a[cell][7];
        hm[8] = base + a[cell][2] + a[cell][4] + a[cell][8];
#pragma unroll
        for (int c = 0; c < 9; c++)
            s_hcat[cell][c][tid] = hm[c] > 0.f ? hm[c] : 0.f;
    }
    __syncthreads();

    if (tid < 108) {
        int cell = tid / 27;
        int r    = tid % 27;
        int ch   = r / 9;
        int cat  = r % 9;
        const float4* wc4 = reinterpret_cast<const float4*>(&w2[ch*128]);
        const float*  hc  = &s_hcat[cell][cat][0];
        float s = 0.f;
#pragma unroll
        for (int q = 0; q < 32; q++) {
            float4 wv = wc4[q];
            s = fmaf(wv.x, hc[4*q + 0], s);
            s = fmaf(wv.y, hc[4*q + 1], s);
            s = fmaf(wv.z, hc[4*q + 2], s);
            s = fmaf(wv.w, hc[4*q + 3], s);
        }
        s_rgb[cell][r] = s + b2[ch];
    }
    __syncthreads();

    for (int p = tid; p < 3072; p += 128) {
        int cell = p / 768;
        int rem  = p % 768;
        int ch = rem >> 8, r = (rem >> 4) & 15, c = rem & 15;
        int n = n0 + cell;
        int b = n >> 6, gh = (n >> 3) & 7, gw = n & 7;
        int rcat = (r == 0) ? 0 : ((r == 15) ? 2 : 1);
        int ccat = (c == 0) ? 0 : ((c == 15) ? 2 : 1);
        out[XHAT_OFF + ((b*3 + ch)*128 + gh*16 + r)*128 + gw*16 + c]
            = s_rgb[cell][ch*9 + rcat*3 + ccat];
    }
}

// ---------------- launch ----------------------------------------------------
extern "C" void kernel_launch(void* const* d_in, const int* in_sizes, int n_in,
                              void* d_out, int out_size)
{
    const float* x        = (const float*)d_in[0];
    const float* enc_w1   = (const float*)d_in[1];
    const float* enc_b1   = (const float*)d_in[2];
    const float* enc_w2   = (const float*)d_in[3];
    const float* enc_b2   = (const float*)d_in[4];
    const float* proj_w   = (const float*)d_in[5];
    const float* proj_b   = (const float*)d_in[6];
    const float* codebook = (const float*)d_in[7];
    const float* dproj_w  = (const float*)d_in[8];
    const float* dproj_b  = (const float*)d_in[9];
    const float* dconv1_w = (const float*)d_in[10];
    const float* dconv1_b = (const float*)d_in[11];
    const float* dconv2_w = (const float*)d_in[12];
    const float* dconv2_b = (const float*)d_in[13];
    float* out = (float*)d_out;

    conv1_kernel<<<dim3(2, 64, 32), 128>>>(x, enc_w1, enc_b1);
    w2t_kernel<<<576, 256>>>(enc_w2);
    conv2_kernel<<<dim3(32, 32), 256>>>(enc_b2);
    pool_kernel<<<1024, 256>>>();
    wprep_kernel<<<128, 128>>>(dconv1_w);
    projvq_kernel<<<2048, 128>>>(proj_w, proj_b, codebook, dproj_w, dproj_b, out);
    loss_kernel<<<1, 1024>>>(out);
    dec_kernel<<<512, 128>>>(dconv1_b, dconv2_w, dconv2_b, out);
}